// round 15
// baseline (speedup 1.0000x reference)
#include <cuda_runtime.h>

// filtfilt, 2nd-order Butterworth, odd ext padlen=9, zero init state.
// Linearity => max|x| normalization cancels; omitted.
// Warm-up truncation: |pole|=3^-0.5, 3^-8 = 1.5e-4 << 1e-3 tolerance.
// R14: float4 gmem staging (interior), float4 warm-up loads, tid127
//      extension through xchg (uniform backward warm-up), dead-state kept4_ns.

#define T_THREADS 128
#define CHUNK_C   32
#define S_OUT     (T_THREADS * CHUNK_C)   // 4096
#define W_WARM    16
#define PADLEN    9
#define N_SAMP    32768
#define E_LEN     (N_SAMP + 2 * PADLEN)   // 32786
#define N_CHUNKS  (N_SAMP / S_OUT)        // 8
#define E_MAX     (S_OUT + 2 * W_WARM)    // 4128
#define E_PHYS    4648                    // PH(4127)=4639, + slack
#define XSTRIDE   17
#define X_SIZE    ((T_THREADS + 1) * XSTRIDE)   // 2193 (slot 128 = tid127 ext)

// ---- compile-time constants (derived in double, folded) ----
#define B0d 0.0976310729378175
#define B1d 0.195262145875635
#define B2d 0.0976310729378175
#define A1d (-0.9428090415820634)
#define A2d (0.33333333333333337)
#define D1d (-(A1d))
#define D2d (-(A2d))
#define C1d (B1d - (A1d) * B0d)
#define C2d (B2d - (A2d) * B0d)
#define M2_11d (D1d*D1d + D2d)
#define M2_12d (D1d)
#define M2_21d (D2d*D1d)
#define M2_22d (D2d)
#define M3_11d (M2_11d*D1d + M2_12d*D2d)
#define M3_12d (M2_11d)
#define M3_21d (M2_21d*D1d + M2_22d*D2d)
#define M3_22d (M2_21d)
#define M4_11d (M3_11d*D1d + M3_12d*D2d)
#define M4_12d (M3_11d)
#define M4_21d (M3_21d*D1d + M3_22d*D2d)
#define M4_22d (M3_21d)
#define W2_1d (D1d*C1d + C2d)
#define W2_2d (D2d*C1d)
#define W1_1d (M2_11d*C1d + M2_12d*C2d)
#define W1_2d (M2_21d*C1d + M2_22d*C2d)
#define W0_1d (M3_11d*C1d + M3_12d*C2d)
#define W0_2d (M3_21d*C1d + M3_22d*C2d)

#define fB0    ((float)(B0d))
#define fD1    ((float)(D1d))
#define fD2    ((float)(D2d))
#define fC1    ((float)(C1d))
#define fC2    ((float)(C2d))
#define fM2_11 ((float)(M2_11d))
#define fM2_12 ((float)(M2_12d))
#define fM3_11 ((float)(M3_11d))
#define fM3_12 ((float)(M3_12d))
#define fM4_11 ((float)(M4_11d))
#define fM4_12 ((float)(M4_12d))
#define fM4_21 ((float)(M4_21d))
#define fM4_22 ((float)(M4_22d))
#define fW2_1  ((float)(W2_1d))
#define fW2_2  ((float)(W2_2d))
#define fW1_1  ((float)(W1_1d))
#define fW1_2  ((float)(W1_2d))
#define fW0_1  ((float)(W0_1d))
#define fW0_2  ((float)(W0_2d))

// physical smem word: groups of 32 words padded to 36 (lane stride 144B,
// conflict-free for 32-bit and 128-bit accesses)
__device__ __forceinline__ int PH(int i) { return i + ((i >> 5) << 2); }

// advance state over 4 samples (no outputs)
__device__ __forceinline__ void warm4(float v0, float v1, float v2, float v3,
                                      float& z1, float& z2)
{
    float E1 = fmaf(fW0_1, v0, fmaf(fW1_1, v1, fmaf(fW2_1, v2, fC1 * v3)));
    float E2 = fmaf(fW0_2, v0, fmaf(fW1_2, v1, fmaf(fW2_2, v2, fC2 * v3)));
    float nz1 = fmaf(fM4_11, z1, fmaf(fM4_12, z2, E1));
    z2        = fmaf(fM4_21, z1, fmaf(fM4_22, z2, E2));
    z1 = nz1;
}

// advance over 4 samples, replacing inputs with outputs (in registers)
__device__ __forceinline__ void kept4(float& v0, float& v1, float& v2, float& v3,
                                      float& z1, float& z2)
{
    float e0 = v0, e1 = v1, e2 = v2, e3 = v3;
    float E1 = fmaf(fW0_1, e0, fmaf(fW1_1, e1, fmaf(fW2_1, e2, fC1 * e3)));
    float E2 = fmaf(fW0_2, e0, fmaf(fW1_2, e1, fmaf(fW2_2, e2, fC2 * e3)));
    float z1a = fmaf(fD1,    z1, fmaf(fC1,    e0, z2));
    float z1b = fmaf(fM2_11, z1, fmaf(fM2_12, z2, fmaf(fW2_1, e0, fC1 * e1)));
    float z1c = fmaf(fM3_11, z1, fmaf(fM3_12, z2, fmaf(fW1_1, e0, fmaf(fW2_1, e1, fC1 * e2))));
    v0 = fmaf(fB0, e0, z1);
    v1 = fmaf(fB0, e1, z1a);
    v2 = fmaf(fB0, e2, z1b);
    v3 = fmaf(fB0, e3, z1c);
    float nz1 = fmaf(fM4_11, z1, fmaf(fM4_12, z2, E1));
    z2        = fmaf(fM4_21, z1, fmaf(fM4_22, z2, E2));
    z1 = nz1;
}

// same but final state is dead (last block of a pass): no state update
__device__ __forceinline__ void kept4_ns(float& v0, float& v1, float& v2, float& v3,
                                         float z1, float z2)
{
    float e0 = v0, e1 = v1, e2 = v2, e3 = v3;
    float z1a = fmaf(fD1,    z1, fmaf(fC1,    e0, z2));
    float z1b = fmaf(fM2_11, z1, fmaf(fM2_12, z2, fmaf(fW2_1, e0, fC1 * e1)));
    float z1c = fmaf(fM3_11, z1, fmaf(fM3_12, z2, fmaf(fW1_1, e0, fmaf(fW2_1, e1, fC1 * e2))));
    v0 = fmaf(fB0, e0, z1);
    v1 = fmaf(fB0, e1, z1a);
    v2 = fmaf(fB0, e2, z1b);
    v3 = fmaf(fB0, e3, z1c);
}

__global__ void __launch_bounds__(T_THREADS, 8)
filtfilt_kernel(const float* __restrict__ x, float* __restrict__ out)
{
    __shared__ __align__(16) float buf[E_PHYS];
    __shared__ float xchg[X_SIZE];

    const int row   = blockIdx.y;
    const int chunk = blockIdx.x;
    const int tid   = threadIdx.x;

    const float* xr   = x   + (long)row * N_SAMP;
    float*       outr = out + (long)row * N_SAMP;

    const int t0 = PADLEN + chunk * S_OUT;

    // ---- stage extended signal; buf[i] <-> t = t0 - W + i ----
    if (chunk != 0 && chunk != N_CHUNKS - 1) {
        // interior: src offset = chunk*S_OUT - 16, multiple of 16 floats -> 64B aligned
        const float4* src4 = reinterpret_cast<const float4*>(xr + (chunk * S_OUT - W_WARM));
        #pragma unroll
        for (int k = 0; k < (E_MAX / 4 + T_THREADS - 1) / T_THREADS; ++k) {  // 9
            int idx = tid + k * T_THREADS;
            if (idx < E_MAX / 4) {   // 1032
                float4 v = src4[idx];
                // PH(4*idx) = 4*idx + ((idx>>3)<<2); 4-word run stays in one group
                *reinterpret_cast<float4*>(&buf[4 * idx + ((idx >> 3) << 2)]) = v;
            }
        }
    } else {
        for (int i = tid; i < E_MAX; i += T_THREADS) {
            int t = t0 - W_WARM + i;
            float v = 0.0f;
            if (t >= PADLEN) {
                if (t < PADLEN + N_SAMP)
                    v = xr[t - PADLEN];
                else if (t < E_LEN)
                    v = 2.0f * xr[N_SAMP - 1] - xr[2 * N_SAMP + PADLEN - 2 - t];
                // t >= E_LEN stays 0
            } else if (t >= 0) {
                v = 2.0f * xr[0] - xr[PADLEN - t];
            }
            // t < 0 stays 0 (exact: zero input + zero state)
            buf[PH(i)] = v;
        }
    }
    __syncthreads();

    float* bp = buf + 36 * tid;          // thread-local padded base (16B-aligned)
    const int u = t0 + tid * CHUNK_C;    // first kept sample (e-space)
    float z1, z2;
    float ev[CHUNK_C];                   // inputs -> y1 -> y2, all in registers

    // ================= forward pass =================
    z1 = 0.0f; z2 = 0.0f;
    {   // warm-up: 4x LDS.128 then register-only
        float4 w0 = *reinterpret_cast<const float4*>(bp + 0);
        float4 w1 = *reinterpret_cast<const float4*>(bp + 4);
        float4 w2 = *reinterpret_cast<const float4*>(bp + 8);
        float4 w3 = *reinterpret_cast<const float4*>(bp + 12);
        warm4(w0.x, w0.y, w0.z, w0.w, z1, z2);
        warm4(w1.x, w1.y, w1.z, w1.w, z1, z2);
        warm4(w2.x, w2.y, w2.z, w2.w, z1, z2);
        warm4(w3.x, w3.y, w3.z, w3.w, z1, z2);
    }

    // kept inputs: logical i = 32*tid + 16 + j -> offsets 16..31 then 36..51
    {
        float4 a0 = *reinterpret_cast<const float4*>(bp + 16);
        float4 a1 = *reinterpret_cast<const float4*>(bp + 20);
        float4 a2 = *reinterpret_cast<const float4*>(bp + 24);
        float4 a3 = *reinterpret_cast<const float4*>(bp + 28);
        float4 a4 = *reinterpret_cast<const float4*>(bp + 36);
        float4 a5 = *reinterpret_cast<const float4*>(bp + 40);
        float4 a6 = *reinterpret_cast<const float4*>(bp + 44);
        float4 a7 = *reinterpret_cast<const float4*>(bp + 48);
        ev[0]=a0.x; ev[1]=a0.y; ev[2]=a0.z; ev[3]=a0.w;
        ev[4]=a1.x; ev[5]=a1.y; ev[6]=a1.z; ev[7]=a1.w;
        ev[8]=a2.x; ev[9]=a2.y; ev[10]=a2.z; ev[11]=a2.w;
        ev[12]=a3.x; ev[13]=a3.y; ev[14]=a3.z; ev[15]=a3.w;
        ev[16]=a4.x; ev[17]=a4.y; ev[18]=a4.z; ev[19]=a4.w;
        ev[20]=a5.x; ev[21]=a5.y; ev[22]=a5.z; ev[23]=a5.w;
        ev[24]=a6.x; ev[25]=a6.y; ev[26]=a6.z; ev[27]=a6.w;
        ev[28]=a7.x; ev[29]=a7.y; ev[30]=a7.z; ev[31]=a7.w;
    }
    #pragma unroll
    for (int b = 0; b < CHUNK_C / 4; ++b)
        kept4(ev[4*b], ev[4*b+1], ev[4*b+2], ev[4*b+3], z1, z2);
    // ev now holds y1 for [u, u+32)

    // exchange: first W y1 values -> left neighbor's backward warm-up.
    // tid127 additionally continues the recurrence over the next W inputs and
    // publishes the extension y1 in slot 128 (zeroed past E_LEN: exact tail).
    #pragma unroll
    for (int j = 0; j < W_WARM; ++j)
        xchg[XSTRIDE * tid + j] = ev[j];
    if (tid == T_THREADS - 1) {
        float zz1 = z1, zz2 = z2;
        #pragma unroll
        for (int j = 0; j < W_WARM; ++j) {
            float e = bp[52 + j];   // logical i = 4112+j
            float y = fmaf(fB0, e, zz1);
            float nz1 = fmaf(fD1, zz1, fmaf(fC1, e, zz2));
            zz2 = fmaf(fD2, zz1, fC2 * e);
            zz1 = nz1;
            xchg[XSTRIDE * T_THREADS + j] = (u + CHUNK_C + j < E_LEN) ? y : 0.0f;
        }
    }
    __syncthreads();

    // ================= backward pass =================
    z1 = 0.0f; z2 = 0.0f;
    {
        const float* xc = xchg + XSTRIDE * (tid + 1);   // y1[u+32+j], j=0..15
        float p0=xc[0], p1=xc[1], p2=xc[2],  p3=xc[3],  p4=xc[4],  p5=xc[5],  p6=xc[6],  p7=xc[7];
        float p8=xc[8], p9=xc[9], pa=xc[10], pb=xc[11], pc=xc[12], pd=xc[13], pe=xc[14], pf=xc[15];
        warm4(pf, pe, pd, pc, z1, z2);
        warm4(pb, pa, p9, p8, z1, z2);
        warm4(p7, p6, p5, p4, z1, z2);
        warm4(p3, p2, p1, p0, z1, z2);
    }
    #pragma unroll
    for (int b = 0; b < CHUNK_C / 4 - 1; ++b)
        kept4(ev[31-4*b], ev[30-4*b], ev[29-4*b], ev[28-4*b], z1, z2);
    kept4_ns(ev[3], ev[2], ev[1], ev[0], z1, z2);   // final state dead
    // ev now holds y2 for [u, u+32)

    // stage y2: output position 32*tid+j -> word 36*tid+j (own group, float4)
    {
        float4 s;
        s.x=ev[0];  s.y=ev[1];  s.z=ev[2];  s.w=ev[3];  *reinterpret_cast<float4*>(bp+0)  = s;
        s.x=ev[4];  s.y=ev[5];  s.z=ev[6];  s.w=ev[7];  *reinterpret_cast<float4*>(bp+4)  = s;
        s.x=ev[8];  s.y=ev[9];  s.z=ev[10]; s.w=ev[11]; *reinterpret_cast<float4*>(bp+8)  = s;
        s.x=ev[12]; s.y=ev[13]; s.z=ev[14]; s.w=ev[15]; *reinterpret_cast<float4*>(bp+12) = s;
        s.x=ev[16]; s.y=ev[17]; s.z=ev[18]; s.w=ev[19]; *reinterpret_cast<float4*>(bp+16) = s;
        s.x=ev[20]; s.y=ev[21]; s.z=ev[22]; s.w=ev[23]; *reinterpret_cast<float4*>(bp+20) = s;
        s.x=ev[24]; s.y=ev[25]; s.z=ev[26]; s.w=ev[27]; *reinterpret_cast<float4*>(bp+24) = s;
        s.x=ev[28]; s.y=ev[29]; s.z=ev[30]; s.w=ev[31]; *reinterpret_cast<float4*>(bp+28) = s;
    }
    __syncthreads();

    // ---- coalesced float4 writeout ----
    float4* o4 = (float4*)(outr + (t0 - PADLEN));
    #pragma unroll
    for (int k = 0; k < S_OUT / 4 / T_THREADS; ++k) {     // 8 iters
        int e = tid + k * T_THREADS;
        float4 v = *reinterpret_cast<const float4*>(&buf[4 * e + ((e >> 3) << 2)]);
        o4[e] = v;
    }
}

extern "C" void kernel_launch(void* const* d_in, const int* in_sizes, int n_in,
                              void* d_out, int out_size)
{
    const float* x = (const float*)d_in[0];
    float* out = (float*)d_out;

    const int rows = in_sizes[0] / N_SAMP;  // 1024
    dim3 grid(N_CHUNKS, rows);
    filtfilt_kernel<<<grid, T_THREADS>>>(x, out);
}

// round 16
// speedup vs baseline: 1.0008x; 1.0008x over previous
#include <cuda_runtime.h>

// filtfilt, 2nd-order Butterworth, odd ext padlen=9, zero init state.
// Linearity => max|x| normalization cancels; omitted.
// Warm-up truncation: |pole|=3^-0.5, 3^-8 = 1.5e-4 << 1e-3 tolerance.
// R16: cp.async staging (no LDG register landing / L1tex queue), T=256 C=16
//      (16-reg ev), xchg eliminated (boundary y1 through buf slot reuse).

#define T_THREADS 256
#define CHUNK_C   16
#define S_OUT     4096
#define W_WARM    16
#define PADLEN    9
#define N_SAMP    32768
#define E_LEN     (N_SAMP + 2 * PADLEN)   // 32786
#define N_CHUNKS  (N_SAMP / S_OUT)        // 8
#define E_MAX     (S_OUT + 2 * W_WARM)    // 4128 logical words
#define N_GROUPS  (E_MAX / 32)            // 129
#define E_PHYS    (N_GROUPS * 36)         // 4644 physical words (18.6 KB)

// ---- compile-time constants (derived in double, folded) ----
#define B0d 0.0976310729378175
#define B1d 0.195262145875635
#define B2d 0.0976310729378175
#define A1d (-0.9428090415820634)
#define A2d (0.33333333333333337)
#define D1d (-(A1d))
#define D2d (-(A2d))
#define C1d (B1d - (A1d) * B0d)
#define C2d (B2d - (A2d) * B0d)
#define M2_11d (D1d*D1d + D2d)
#define M2_12d (D1d)
#define M2_21d (D2d*D1d)
#define M2_22d (D2d)
#define M3_11d (M2_11d*D1d + M2_12d*D2d)
#define M3_12d (M2_11d)
#define M3_21d (M2_21d*D1d + M2_22d*D2d)
#define M3_22d (M2_21d)
#define M4_11d (M3_11d*D1d + M3_12d*D2d)
#define M4_12d (M3_11d)
#define M4_21d (M3_21d*D1d + M3_22d*D2d)
#define M4_22d (M3_21d)
#define W2_1d (D1d*C1d + C2d)
#define W2_2d (D2d*C1d)
#define W1_1d (M2_11d*C1d + M2_12d*C2d)
#define W1_2d (M2_21d*C1d + M2_22d*C2d)
#define W0_1d (M3_11d*C1d + M3_12d*C2d)
#define W0_2d (M3_21d*C1d + M3_22d*C2d)

#define fB0    ((float)(B0d))
#define fD1    ((float)(D1d))
#define fD2    ((float)(D2d))
#define fC1    ((float)(C1d))
#define fC2    ((float)(C2d))
#define fM2_11 ((float)(M2_11d))
#define fM2_12 ((float)(M2_12d))
#define fM3_11 ((float)(M3_11d))
#define fM3_12 ((float)(M3_12d))
#define fM4_11 ((float)(M4_11d))
#define fM4_12 ((float)(M4_12d))
#define fM4_21 ((float)(M4_21d))
#define fM4_22 ((float)(M4_22d))
#define fW2_1  ((float)(W2_1d))
#define fW2_2  ((float)(W2_2d))
#define fW1_1  ((float)(W1_1d))
#define fW1_2  ((float)(W1_2d))
#define fW0_1  ((float)(W0_1d))
#define fW0_2  ((float)(W0_2d))

// logical word i -> physical word (groups of 32 padded to 36; lane stride 144B,
// conflict-free for 32-bit and 128-bit access patterns used below)
__device__ __forceinline__ int PH(int i)  { return 36 * (i >> 5) + (i & 31); }
// float4 index idx (logical word 4*idx) -> physical word
__device__ __forceinline__ int PHV(int idx) { return 36 * (idx >> 3) + 4 * (idx & 7); }

__device__ __forceinline__ void cp_async16(unsigned saddr, const void* gptr)
{
    asm volatile("cp.async.cg.shared.global [%0], [%1], 16;"
                 :: "r"(saddr), "l"(gptr));
}

// advance state over 4 samples (no outputs)
__device__ __forceinline__ void warm4(float v0, float v1, float v2, float v3,
                                      float& z1, float& z2)
{
    float E1 = fmaf(fW0_1, v0, fmaf(fW1_1, v1, fmaf(fW2_1, v2, fC1 * v3)));
    float E2 = fmaf(fW0_2, v0, fmaf(fW1_2, v1, fmaf(fW2_2, v2, fC2 * v3)));
    float nz1 = fmaf(fM4_11, z1, fmaf(fM4_12, z2, E1));
    z2        = fmaf(fM4_21, z1, fmaf(fM4_22, z2, E2));
    z1 = nz1;
}

// advance over 4 samples, replacing inputs with outputs (in registers)
__device__ __forceinline__ void kept4(float& v0, float& v1, float& v2, float& v3,
                                      float& z1, float& z2)
{
    float e0 = v0, e1 = v1, e2 = v2, e3 = v3;
    float E1 = fmaf(fW0_1, e0, fmaf(fW1_1, e1, fmaf(fW2_1, e2, fC1 * e3)));
    float E2 = fmaf(fW0_2, e0, fmaf(fW1_2, e1, fmaf(fW2_2, e2, fC2 * e3)));
    float z1a = fmaf(fD1,    z1, fmaf(fC1,    e0, z2));
    float z1b = fmaf(fM2_11, z1, fmaf(fM2_12, z2, fmaf(fW2_1, e0, fC1 * e1)));
    float z1c = fmaf(fM3_11, z1, fmaf(fM3_12, z2, fmaf(fW1_1, e0, fmaf(fW2_1, e1, fC1 * e2))));
    v0 = fmaf(fB0, e0, z1);
    v1 = fmaf(fB0, e1, z1a);
    v2 = fmaf(fB0, e2, z1b);
    v3 = fmaf(fB0, e3, z1c);
    float nz1 = fmaf(fM4_11, z1, fmaf(fM4_12, z2, E1));
    z2        = fmaf(fM4_21, z1, fmaf(fM4_22, z2, E2));
    z1 = nz1;
}

// same but final state is dead (last block of a pass)
__device__ __forceinline__ void kept4_ns(float& v0, float& v1, float& v2, float& v3,
                                         float z1, float z2)
{
    float e0 = v0, e1 = v1, e2 = v2, e3 = v3;
    float z1a = fmaf(fD1,    z1, fmaf(fC1,    e0, z2));
    float z1b = fmaf(fM2_11, z1, fmaf(fM2_12, z2, fmaf(fW2_1, e0, fC1 * e1)));
    float z1c = fmaf(fM3_11, z1, fmaf(fM3_12, z2, fmaf(fW1_1, e0, fmaf(fW2_1, e1, fC1 * e2))));
    v0 = fmaf(fB0, e0, z1);
    v1 = fmaf(fB0, e1, z1a);
    v2 = fmaf(fB0, e2, z1b);
    v3 = fmaf(fB0, e3, z1c);
}

__global__ void __launch_bounds__(T_THREADS, 5)
filtfilt_kernel(const float* __restrict__ x, float* __restrict__ out)
{
    __shared__ __align__(16) float buf[E_PHYS];

    const int row   = blockIdx.y;
    const int chunk = blockIdx.x;
    const int tid   = threadIdx.x;

    const float* xr   = x   + (long)row * N_SAMP;
    float*       outr = out + (long)row * N_SAMP;

    const int t0 = PADLEN + chunk * S_OUT;

    // ---- stage extended signal; buf logical i <-> t = t0 - W + i ----
    if (chunk != 0 && chunk != N_CHUNKS - 1) {
        // interior: cp.async 16B copies, gmem src 64B-aligned
        const float4* src4 = reinterpret_cast<const float4*>(xr + (chunk * S_OUT - W_WARM));
        unsigned sbase = (unsigned)__cvta_generic_to_shared(buf);
        #pragma unroll
        for (int k = 0; k < (E_MAX / 4 + T_THREADS - 1) / T_THREADS; ++k) {  // 5
            int idx = tid + k * T_THREADS;
            if (idx < E_MAX / 4)   // 1032
                cp_async16(sbase + 4u * (unsigned)PHV(idx), src4 + idx);
        }
        asm volatile("cp.async.commit_group;");
        asm volatile("cp.async.wait_group 0;");
    } else {
        for (int i = tid; i < E_MAX; i += T_THREADS) {
            int t = t0 - W_WARM + i;
            float v = 0.0f;
            if (t >= PADLEN) {
                if (t < PADLEN + N_SAMP)
                    v = xr[t - PADLEN];
                else if (t < E_LEN)
                    v = 2.0f * xr[N_SAMP - 1] - xr[2 * N_SAMP + PADLEN - 2 - t];
                // t >= E_LEN stays 0 (exact zero-state tail)
            } else if (t >= 0) {
                v = 2.0f * xr[0] - xr[PADLEN - t];
            }
            // t < 0 stays 0 (exact: zero input + zero state)
            buf[PH(i)] = v;
        }
    }
    __syncthreads();   // S1

    // thread t: warm inputs logical 16t..16t+15, kept logical 16t+16..16t+31
    const int pw = 36 * (tid >> 1) + 16 * (tid & 1);               // phys of 16*tid
    const int pk = 36 * ((tid + 1) >> 1) + 16 * ((tid + 1) & 1);   // phys of 16*(tid+1)
    const int pb = 36 * ((tid + 2) >> 1) + 16 * ((tid + 2) & 1);   // phys of 16*(tid+2)

    float ev[CHUNK_C];
    float z1 = 0.0f, z2 = 0.0f;

    // ================= forward pass =================
    {
        float4 w0 = *reinterpret_cast<const float4*>(buf + pw + 0);
        float4 w1 = *reinterpret_cast<const float4*>(buf + pw + 4);
        float4 w2 = *reinterpret_cast<const float4*>(buf + pw + 8);
        float4 w3 = *reinterpret_cast<const float4*>(buf + pw + 12);
        float4 a0 = *reinterpret_cast<const float4*>(buf + pk + 0);
        float4 a1 = *reinterpret_cast<const float4*>(buf + pk + 4);
        float4 a2 = *reinterpret_cast<const float4*>(buf + pk + 8);
        float4 a3 = *reinterpret_cast<const float4*>(buf + pk + 12);
        warm4(w0.x, w0.y, w0.z, w0.w, z1, z2);
        warm4(w1.x, w1.y, w1.z, w1.w, z1, z2);
        warm4(w2.x, w2.y, w2.z, w2.w, z1, z2);
        warm4(w3.x, w3.y, w3.z, w3.w, z1, z2);
        ev[0]=a0.x;  ev[1]=a0.y;  ev[2]=a0.z;  ev[3]=a0.w;
        ev[4]=a1.x;  ev[5]=a1.y;  ev[6]=a1.z;  ev[7]=a1.w;
        ev[8]=a2.x;  ev[9]=a2.y;  ev[10]=a2.z; ev[11]=a2.w;
        ev[12]=a3.x; ev[13]=a3.y; ev[14]=a3.z; ev[15]=a3.w;
    }
    #pragma unroll
    for (int b = 0; b < CHUNK_C / 4; ++b)
        kept4(ev[4*b], ev[4*b+1], ev[4*b+2], ev[4*b+3], z1, z2);
    // ev = y1 for this thread's kept samples
    __syncthreads();   // S2: all input loads done -> safe to overwrite

    // publish y1 into own kept slots (read by left neighbor's backward warm-up)
    {
        float4 s;
        s.x=ev[0];  s.y=ev[1];  s.z=ev[2];  s.w=ev[3];  *reinterpret_cast<float4*>(buf+pk+0)  = s;
        s.x=ev[4];  s.y=ev[5];  s.z=ev[6];  s.w=ev[7];  *reinterpret_cast<float4*>(buf+pk+4)  = s;
        s.x=ev[8];  s.y=ev[9];  s.z=ev[10]; s.w=ev[11]; *reinterpret_cast<float4*>(buf+pk+8)  = s;
        s.x=ev[12]; s.y=ev[13]; s.z=ev[14]; s.w=ev[15]; *reinterpret_cast<float4*>(buf+pk+12) = s;
    }
    if (tid == T_THREADS - 1) {
        // continue recurrence over logical 4112..4127 (slots untouched by stores),
        // writing extension y1 in place; zero past E_LEN (exact right edge)
        float zz1 = z1, zz2 = z2;
        #pragma unroll
        for (int j = 0; j < W_WARM; ++j) {
            int p = 4624 + j;                 // PH(4112 + j)
            float e = buf[p];
            float y = fmaf(fB0, e, zz1);
            float nz1 = fmaf(fD1, zz1, fmaf(fC1, e, zz2));
            zz2 = fmaf(fD2, zz1, fC2 * e);
            zz1 = nz1;
            buf[p] = (t0 + S_OUT + j < E_LEN) ? y : 0.0f;
        }
    }
    __syncthreads();   // S3

    // ================= backward pass =================
    z1 = 0.0f; z2 = 0.0f;
    {
        float4 p0 = *reinterpret_cast<const float4*>(buf + pb + 0);
        float4 p1 = *reinterpret_cast<const float4*>(buf + pb + 4);
        float4 p2 = *reinterpret_cast<const float4*>(buf + pb + 8);
        float4 p3 = *reinterpret_cast<const float4*>(buf + pb + 12);
        warm4(p3.w, p3.z, p3.y, p3.x, z1, z2);
        warm4(p2.w, p2.z, p2.y, p2.x, z1, z2);
        warm4(p1.w, p1.z, p1.y, p1.x, z1, z2);
        warm4(p0.w, p0.z, p0.y, p0.x, z1, z2);
    }
    #pragma unroll
    for (int b = 0; b < CHUNK_C / 4 - 1; ++b)
        kept4(ev[15-4*b], ev[14-4*b], ev[13-4*b], ev[12-4*b], z1, z2);
    kept4_ns(ev[3], ev[2], ev[1], ev[0], z1, z2);   // final state dead
    // ev = y2
    __syncthreads();   // S4: neighbors' backward-warm loads done

    // stage y2 into own warm slots: output sample 16*tid+j <-> logical 16*tid+j
    {
        float4 s;
        s.x=ev[0];  s.y=ev[1];  s.z=ev[2];  s.w=ev[3];  *reinterpret_cast<float4*>(buf+pw+0)  = s;
        s.x=ev[4];  s.y=ev[5];  s.z=ev[6];  s.w=ev[7];  *reinterpret_cast<float4*>(buf+pw+4)  = s;
        s.x=ev[8];  s.y=ev[9];  s.z=ev[10]; s.w=ev[11]; *reinterpret_cast<float4*>(buf+pw+8)  = s;
        s.x=ev[12]; s.y=ev[13]; s.z=ev[14]; s.w=ev[15]; *reinterpret_cast<float4*>(buf+pw+12) = s;
    }
    __syncthreads();   // S5

    // ---- coalesced float4 writeout ----
    float4* o4 = (float4*)(outr + chunk * S_OUT);
    #pragma unroll
    for (int k = 0; k < S_OUT / 4 / T_THREADS; ++k) {   // 4 iters
        int e = tid + k * T_THREADS;
        float4 v = *reinterpret_cast<const float4*>(buf + PHV(e));
        o4[e] = v;
    }
}

extern "C" void kernel_launch(void* const* d_in, const int* in_sizes, int n_in,
                              void* d_out, int out_size)
{
    const float* x = (const float*)d_in[0];
    float* out = (float*)d_out;

    const int rows = in_sizes[0] / N_SAMP;  // 1024
    dim3 grid(N_CHUNKS, rows);
    filtfilt_kernel<<<grid, T_THREADS>>>(x, out);
}

// round 17
// speedup vs baseline: 1.3191x; 1.3180x over previous
#include <cuda_runtime.h>

// filtfilt, 2nd-order Butterworth, odd ext padlen=9, zero init state.
// Linearity => max|x| normalization cancels; omitted.
// Warm-up truncation: |pole|=3^-0.5, 3^-8 = 1.5e-4 << 1e-3 tolerance.
// R17: software pipeline — each block processes 4 independent (row,chunk)
//      tiles with double-buffered cp.async; loads of tile i+1 overlap
//      compute of tile i. Compute structure identical to R16.

#define T_THREADS 256
#define CHUNK_C   16
#define S_OUT     4096
#define W_WARM    16
#define PADLEN    9
#define N_SAMP    32768
#define E_LEN     (N_SAMP + 2 * PADLEN)   // 32786
#define N_CHUNKS  (N_SAMP / S_OUT)        // 8
#define E_MAX     (S_OUT + 2 * W_WARM)    // 4128 logical words
#define N_GROUPS  (E_MAX / 32)            // 129
#define E_PHYS    (N_GROUPS * 36)         // 4644 physical words
#define GRID_X    2048
#define K_TILES   4                        // rows row0, row0+256, +512, +768

// ---- compile-time constants (derived in double, folded) ----
#define B0d 0.0976310729378175
#define B1d 0.195262145875635
#define B2d 0.0976310729378175
#define A1d (-0.9428090415820634)
#define A2d (0.33333333333333337)
#define D1d (-(A1d))
#define D2d (-(A2d))
#define C1d (B1d - (A1d) * B0d)
#define C2d (B2d - (A2d) * B0d)
#define M2_11d (D1d*D1d + D2d)
#define M2_12d (D1d)
#define M2_21d (D2d*D1d)
#define M2_22d (D2d)
#define M3_11d (M2_11d*D1d + M2_12d*D2d)
#define M3_12d (M2_11d)
#define M3_21d (M2_21d*D1d + M2_22d*D2d)
#define M3_22d (M2_21d)
#define M4_11d (M3_11d*D1d + M3_12d*D2d)
#define M4_12d (M3_11d)
#define M4_21d (M3_21d*D1d + M3_22d*D2d)
#define M4_22d (M3_21d)
#define W2_1d (D1d*C1d + C2d)
#define W2_2d (D2d*C1d)
#define W1_1d (M2_11d*C1d + M2_12d*C2d)
#define W1_2d (M2_21d*C1d + M2_22d*C2d)
#define W0_1d (M3_11d*C1d + M3_12d*C2d)
#define W0_2d (M3_21d*C1d + M3_22d*C2d)

#define fB0    ((float)(B0d))
#define fD1    ((float)(D1d))
#define fD2    ((float)(D2d))
#define fC1    ((float)(C1d))
#define fC2    ((float)(C2d))
#define fM2_11 ((float)(M2_11d))
#define fM2_12 ((float)(M2_12d))
#define fM3_11 ((float)(M3_11d))
#define fM3_12 ((float)(M3_12d))
#define fM4_11 ((float)(M4_11d))
#define fM4_12 ((float)(M4_12d))
#define fM4_21 ((float)(M4_21d))
#define fM4_22 ((float)(M4_22d))
#define fW2_1  ((float)(W2_1d))
#define fW2_2  ((float)(W2_2d))
#define fW1_1  ((float)(W1_1d))
#define fW1_2  ((float)(W1_2d))
#define fW0_1  ((float)(W0_1d))
#define fW0_2  ((float)(W0_2d))

__device__ __forceinline__ int PH(int i)   { return 36 * (i >> 5) + (i & 31); }
__device__ __forceinline__ int PHV(int idx){ return 36 * (idx >> 3) + 4 * (idx & 7); }

__device__ __forceinline__ void cp_async16(unsigned saddr, const void* gptr)
{
    asm volatile("cp.async.cg.shared.global [%0], [%1], 16;" :: "r"(saddr), "l"(gptr));
}
__device__ __forceinline__ void cp_commit() { asm volatile("cp.async.commit_group;"); }
__device__ __forceinline__ void cp_wait1()  { asm volatile("cp.async.wait_group 1;"); }
__device__ __forceinline__ void cp_wait0()  { asm volatile("cp.async.wait_group 0;"); }

__device__ __forceinline__ void warm4(float v0, float v1, float v2, float v3,
                                      float& z1, float& z2)
{
    float E1 = fmaf(fW0_1, v0, fmaf(fW1_1, v1, fmaf(fW2_1, v2, fC1 * v3)));
    float E2 = fmaf(fW0_2, v0, fmaf(fW1_2, v1, fmaf(fW2_2, v2, fC2 * v3)));
    float nz1 = fmaf(fM4_11, z1, fmaf(fM4_12, z2, E1));
    z2        = fmaf(fM4_21, z1, fmaf(fM4_22, z2, E2));
    z1 = nz1;
}

__device__ __forceinline__ void kept4(float& v0, float& v1, float& v2, float& v3,
                                      float& z1, float& z2)
{
    float e0 = v0, e1 = v1, e2 = v2, e3 = v3;
    float E1 = fmaf(fW0_1, e0, fmaf(fW1_1, e1, fmaf(fW2_1, e2, fC1 * e3)));
    float E2 = fmaf(fW0_2, e0, fmaf(fW1_2, e1, fmaf(fW2_2, e2, fC2 * e3)));
    float z1a = fmaf(fD1,    z1, fmaf(fC1,    e0, z2));
    float z1b = fmaf(fM2_11, z1, fmaf(fM2_12, z2, fmaf(fW2_1, e0, fC1 * e1)));
    float z1c = fmaf(fM3_11, z1, fmaf(fM3_12, z2, fmaf(fW1_1, e0, fmaf(fW2_1, e1, fC1 * e2))));
    v0 = fmaf(fB0, e0, z1);
    v1 = fmaf(fB0, e1, z1a);
    v2 = fmaf(fB0, e2, z1b);
    v3 = fmaf(fB0, e3, z1c);
    float nz1 = fmaf(fM4_11, z1, fmaf(fM4_12, z2, E1));
    z2        = fmaf(fM4_21, z1, fmaf(fM4_22, z2, E2));
    z1 = nz1;
}

__device__ __forceinline__ void kept4_ns(float& v0, float& v1, float& v2, float& v3,
                                         float z1, float z2)
{
    float e0 = v0, e1 = v1, e2 = v2, e3 = v3;
    float z1a = fmaf(fD1,    z1, fmaf(fC1,    e0, z2));
    float z1b = fmaf(fM2_11, z1, fmaf(fM2_12, z2, fmaf(fW2_1, e0, fC1 * e1)));
    float z1c = fmaf(fM3_11, z1, fmaf(fM3_12, z2, fmaf(fW1_1, e0, fmaf(fW2_1, e1, fC1 * e2))));
    v0 = fmaf(fB0, e0, z1);
    v1 = fmaf(fB0, e1, z1a);
    v2 = fmaf(fB0, e2, z1b);
    v3 = fmaf(fB0, e3, z1c);
}

// issue the bulk cp.async loads for one tile (aligned interior of the window)
__device__ __forceinline__ void issue_load(float* dst, const float* xr,
                                           int chunk, int tid)
{
    const float4* src4 = reinterpret_cast<const float4*>(xr + (chunk * S_OUT - W_WARM));
    unsigned sbase = (unsigned)__cvta_generic_to_shared(dst);
    const int lo = (chunk == 0) ? 4 : 0;                 // skip pre-signal words
    const int hi = (chunk == N_CHUNKS - 1) ? 1028 : 1032;
    #pragma unroll
    for (int k = 0; k < 5; ++k) {
        int idx = tid + k * T_THREADS;
        if (idx >= lo && idx < hi)
            cp_async16(sbase + 4u * (unsigned)PHV(idx), src4 + idx);
    }
    cp_commit();
}

__global__ void __launch_bounds__(T_THREADS, 5)
filtfilt_kernel(const float* __restrict__ x, float* __restrict__ out)
{
    __shared__ __align__(16) float buf[2][E_PHYS];

    const int tid   = threadIdx.x;
    const int chunk = blockIdx.x & 7;        // constant across this block's tiles
    const int row0  = blockIdx.x >> 3;
    const int t0    = PADLEN + chunk * S_OUT;
    const bool edge = (chunk == 0) || (chunk == N_CHUNKS - 1);

    // per-thread physical bases (constant across tiles)
    const int pw = 36 * (tid >> 1) + 16 * (tid & 1);
    const int pk = 36 * ((tid + 1) >> 1) + 16 * ((tid + 1) & 1);
    const int pb = 36 * ((tid + 2) >> 1) + 16 * ((tid + 2) & 1);

    // prologue: start load of tile 0
    issue_load(buf[0], x + (long)row0 * N_SAMP, chunk, tid);

    #pragma unroll
    for (int it = 0; it < K_TILES; ++it) {
        const int row = row0 + (it << 8);                // +256 per tile
        const float* xr   = x   + (long)row * N_SAMP;
        float*       outr = out + (long)row * N_SAMP;
        float* A = buf[it & 1];

        // start load of next tile into the other buffer, then wait for ours
        if (it + 1 < K_TILES) {
            issue_load(buf[(it + 1) & 1], x + (long)(row + 256) * N_SAMP, chunk, tid);
            cp_wait1();
        } else {
            cp_wait0();
        }
        __syncthreads();   // S1: tile data visible

        // edge patch (uniform branch; block-constant chunk)
        if (edge) {
            if (chunk == 0) {
                if (tid < 16) {   // logical i 0..15 <-> t = i-7
                    float v = (tid < 7) ? 0.0f
                                        : fmaf(2.0f, xr[0], -xr[16 - tid]);
                    A[tid] = v;   // PH(i)=i for i<32
                }
            } else {
                if (tid < 16) {   // logical i 4112..4127 <-> t = 32777+tid
                    int i = 4112 + tid;
                    float v = (i < 4121)
                        ? fmaf(2.0f, xr[N_SAMP - 1], -xr[36878 - i])
                        : 0.0f;   // exact zero tail past E_LEN
                    A[4624 + tid] = v;   // PH(4112+tid)
                }
            }
            __syncthreads();
        }

        float ev[CHUNK_C];
        float z1 = 0.0f, z2 = 0.0f;

        // ================= forward pass =================
        {
            float4 w0 = *reinterpret_cast<const float4*>(A + pw + 0);
            float4 w1 = *reinterpret_cast<const float4*>(A + pw + 4);
            float4 w2 = *reinterpret_cast<const float4*>(A + pw + 8);
            float4 w3 = *reinterpret_cast<const float4*>(A + pw + 12);
            float4 a0 = *reinterpret_cast<const float4*>(A + pk + 0);
            float4 a1 = *reinterpret_cast<const float4*>(A + pk + 4);
            float4 a2 = *reinterpret_cast<const float4*>(A + pk + 8);
            float4 a3 = *reinterpret_cast<const float4*>(A + pk + 12);
            warm4(w0.x, w0.y, w0.z, w0.w, z1, z2);
            warm4(w1.x, w1.y, w1.z, w1.w, z1, z2);
            warm4(w2.x, w2.y, w2.z, w2.w, z1, z2);
            warm4(w3.x, w3.y, w3.z, w3.w, z1, z2);
            ev[0]=a0.x;  ev[1]=a0.y;  ev[2]=a0.z;  ev[3]=a0.w;
            ev[4]=a1.x;  ev[5]=a1.y;  ev[6]=a1.z;  ev[7]=a1.w;
            ev[8]=a2.x;  ev[9]=a2.y;  ev[10]=a2.z; ev[11]=a2.w;
            ev[12]=a3.x; ev[13]=a3.y; ev[14]=a3.z; ev[15]=a3.w;
        }
        #pragma unroll
        for (int b = 0; b < CHUNK_C / 4; ++b)
            kept4(ev[4*b], ev[4*b+1], ev[4*b+2], ev[4*b+3], z1, z2);
        __syncthreads();   // S2: input loads done -> safe to overwrite

        // publish y1 into own kept slots
        {
            float4 s;
            s.x=ev[0];  s.y=ev[1];  s.z=ev[2];  s.w=ev[3];  *reinterpret_cast<float4*>(A+pk+0)  = s;
            s.x=ev[4];  s.y=ev[5];  s.z=ev[6];  s.w=ev[7];  *reinterpret_cast<float4*>(A+pk+4)  = s;
            s.x=ev[8];  s.y=ev[9];  s.z=ev[10]; s.w=ev[11]; *reinterpret_cast<float4*>(A+pk+8)  = s;
            s.x=ev[12]; s.y=ev[13]; s.z=ev[14]; s.w=ev[15]; *reinterpret_cast<float4*>(A+pk+12) = s;
        }
        if (tid == T_THREADS - 1) {
            float zz1 = z1, zz2 = z2;
            #pragma unroll
            for (int j = 0; j < W_WARM; ++j) {
                int p = 4624 + j;                 // PH(4112 + j)
                float e = A[p];
                float y = fmaf(fB0, e, zz1);
                float nz1 = fmaf(fD1, zz1, fmaf(fC1, e, zz2));
                zz2 = fmaf(fD2, zz1, fC2 * e);
                zz1 = nz1;
                A[p] = (t0 + S_OUT + j < E_LEN) ? y : 0.0f;
            }
        }
        __syncthreads();   // S3

        // ================= backward pass =================
        z1 = 0.0f; z2 = 0.0f;
        {
            float4 p0 = *reinterpret_cast<const float4*>(A + pb + 0);
            float4 p1 = *reinterpret_cast<const float4*>(A + pb + 4);
            float4 p2 = *reinterpret_cast<const float4*>(A + pb + 8);
            float4 p3 = *reinterpret_cast<const float4*>(A + pb + 12);
            warm4(p3.w, p3.z, p3.y, p3.x, z1, z2);
            warm4(p2.w, p2.z, p2.y, p2.x, z1, z2);
            warm4(p1.w, p1.z, p1.y, p1.x, z1, z2);
            warm4(p0.w, p0.z, p0.y, p0.x, z1, z2);
        }
        #pragma unroll
        for (int b = 0; b < CHUNK_C / 4 - 1; ++b)
            kept4(ev[15-4*b], ev[14-4*b], ev[13-4*b], ev[12-4*b], z1, z2);
        kept4_ns(ev[3], ev[2], ev[1], ev[0], z1, z2);
        __syncthreads();   // S4: neighbors' backward-warm loads done

        // stage y2 into own warm slots
        {
            float4 s;
            s.x=ev[0];  s.y=ev[1];  s.z=ev[2];  s.w=ev[3];  *reinterpret_cast<float4*>(A+pw+0)  = s;
            s.x=ev[4];  s.y=ev[5];  s.z=ev[6];  s.w=ev[7];  *reinterpret_cast<float4*>(A+pw+4)  = s;
            s.x=ev[8];  s.y=ev[9];  s.z=ev[10]; s.w=ev[11]; *reinterpret_cast<float4*>(A+pw+8)  = s;
            s.x=ev[12]; s.y=ev[13]; s.z=ev[14]; s.w=ev[15]; *reinterpret_cast<float4*>(A+pw+12) = s;
        }
        __syncthreads();   // S5

        // coalesced float4 writeout (STG overlaps next tile's compute)
        float4* o4 = (float4*)(outr + chunk * S_OUT);
        #pragma unroll
        for (int k = 0; k < S_OUT / 4 / T_THREADS; ++k) {
            int e = tid + k * T_THREADS;
            float4 v = *reinterpret_cast<const float4*>(A + PHV(e));
            o4[e] = v;
        }
        __syncthreads();   // S6: A fully consumed before it becomes a load target
    }
}

extern "C" void kernel_launch(void* const* d_in, const int* in_sizes, int n_in,
                              void* d_out, int out_size)
{
    const float* x = (const float*)d_in[0];
    float* out = (float*)d_out;

    filtfilt_kernel<<<GRID_X, T_THREADS>>>(x, out);
}